// round 17
// baseline (speedup 1.0000x reference)
#include <cuda_runtime.h>
#include <cuda_fp16.h>
#include <cstdint>

#define NN 8192
#define PP 49
#define FF 256
#define EE 256
#define HH 256
#define SS 128
#define MTOT (NN * PP)   // 401408
#define NTILES (MTOT / 128)  // 3136

// Scratch (no allocations allowed)
__device__ float  g_x2[NN * EE];      // 8 MB
__device__ __half g_w1h[EE * FF];     // 128 KB fp16 W1
__device__ __half g_w2h[EE * HH];     // 128 KB fp16 W2
__device__ float  g_scores[NN];
__device__ float  g_attn[NN];

// ---------------------------------------------------------------------------
// helpers
// ---------------------------------------------------------------------------
__device__ __forceinline__ uint32_t smem_u32(const void* p) {
    uint32_t a;
    asm("{ .reg .u64 t; cvta.to.shared.u64 t, %1; cvt.u32.u64 %0, t; }" : "=r"(a) : "l"(p));
    return a;
}
__device__ __forceinline__ float ftanh(float x) {   // err ~1e-6
    float e = __expf(2.f * x);
    return 1.f - __fdividef(2.f, e + 1.f);
}
__device__ __forceinline__ float tanha(float x) {   // MUFU tanh
    float y;
    asm("tanh.approx.f32 %0, %1;" : "=f"(y) : "f"(x));
    return y;
}

#define LDSM4(r, addr) \
    asm volatile("ldmatrix.sync.aligned.m8n8.x4.shared.b16 {%0,%1,%2,%3}, [%4];" \
        : "=r"((r)[0]), "=r"((r)[1]), "=r"((r)[2]), "=r"((r)[3]) : "r"(addr))

// f32-acc (k1m)
#define MMA16816(c, a, b0v, b1v) \
    asm volatile("mma.sync.aligned.m16n8k16.row.col.f32.f16.f16.f32 " \
        "{%0,%1,%2,%3},{%4,%5,%6,%7},{%8,%9},{%0,%1,%2,%3};" \
        : "+f"((c)[0]), "+f"((c)[1]), "+f"((c)[2]), "+f"((c)[3]) \
        : "r"((a)[0]), "r"((a)[1]), "r"((a)[2]), "r"((a)[3]), "r"(b0v), "r"(b1v))

// f16-acc (k2, rate-equal per R15; keeps regs <=128 for 2 CTAs/SM)
#define MMA16816F16(c, a, b0v, b1v) \
    asm volatile("mma.sync.aligned.m16n8k16.row.col.f16.f16.f16.f16 " \
        "{%0,%1},{%2,%3,%4,%5},{%6,%7},{%0,%1};" \
        : "+r"((c)[0]), "+r"((c)[1]) \
        : "r"((a)[0]), "r"((a)[1]), "r"((a)[2]), "r"((a)[3]), "r"(b0v), "r"(b1v))

__device__ __forceinline__ uint32_t pack_h2(float a, float b) {
    __half2 h = __floats2half2_rn(a, b);
    return *(uint32_t*)&h;
}

__global__ void kdummy() {}

// ---------------------------------------------------------------------------
// K0: convert W1,W2 -> fp16; zero g_scores.
// ---------------------------------------------------------------------------
__global__ __launch_bounds__(256) void k0_prep(const float* __restrict__ W1,
                                               const float* __restrict__ W2) {
    int i = blockIdx.x * 256 + threadIdx.x;   // 0..65535
    g_w1h[i] = __float2half_rn(W1[i]);
    g_w2h[i] = __float2half_rn(W2[i]);
    if (i < NN) g_scores[i] = 0.f;
}

// ---------------------------------------------------------------------------
// K1M: x2 = tanh(H . W2^T + b2) via fp16 mma (f32 acc).  R13/R14-verified.
// ---------------------------------------------------------------------------
#define M_OFF_B2  0
#define M_OFF_BW  2688
#define M_OFF_A   70272
#define M_A_BUF   10240
#define K1M_SMEM  90752

__global__ __launch_bounds__(256, 2) void k1m_x2(const float* __restrict__ Hm,
                                                 const float* __restrict__ b2) {
    extern __shared__ __align__(16) char smem[];
    float* b2s = (float*)(smem + M_OFF_B2);

    const int tid = threadIdx.x;
    const int w = tid >> 5, lane = tid & 31;
    const int tig = lane & 3, g = lane >> 2;
    const int wm = w >> 2, wn = w & 3;
    const int row0 = blockIdx.x * 128;
    const int e0 = blockIdx.y * 128;

    const float* Xp = Hm + (size_t)(row0 + (tid >> 1)) * HH + (tid & 1) * 16;
    float4 pr0 = *(const float4*)(Xp + 0);
    float4 pr1 = *(const float4*)(Xp + 4);
    float4 pr2 = *(const float4*)(Xp + 8);
    float4 pr3 = *(const float4*)(Xp + 12);

    {
        const uint4* Wp = (const uint4*)(g_w2h + (size_t)e0 * HH);
        for (int i = tid; i < 4096; i += 256) {
            int r = i >> 5, s2 = i & 31;
            *(uint4*)(smem + M_OFF_BW + r * 528 + s2 * 16) = Wp[i];
        }
    }
    if (tid < 128) b2s[tid] = b2[e0 + tid];

    float acc[4][4][4];
#pragma unroll
    for (int mt = 0; mt < 4; mt++)
#pragma unroll
        for (int nt = 0; nt < 4; nt++)
#pragma unroll
            for (int i = 0; i < 4; i++) acc[mt][nt][i] = 0.f;

    const uint32_t sb = smem_u32(smem);
    const int arow = lane & 15, asel = lane >> 4;
    const uint32_t aAddr0 = sb + M_OFF_A + (uint32_t)(wm * 64 + arow) * 80 + asel * 16;
    const int brow = (lane & 7) + ((lane >> 4) << 3), bsel = (lane >> 3) & 1;
    const uint32_t bAddr0 = sb + M_OFF_BW + (uint32_t)(wn * 32 + brow) * 528 + bsel * 16;
    char* stsP = smem + M_OFF_A + (tid >> 1) * 80 + (tid & 1) * 32;

    for (int kc = 0; kc < 8; kc++) {
        const uint32_t bo = (kc & 1) * M_A_BUF;
        {
            uint4 q0, q1;
            q0.x = pack_h2(pr0.x, pr0.y); q0.y = pack_h2(pr0.z, pr0.w);
            q0.z = pack_h2(pr1.x, pr1.y); q0.w = pack_h2(pr1.z, pr1.w);
            q1.x = pack_h2(pr2.x, pr2.y); q1.y = pack_h2(pr2.z, pr2.w);
            q1.z = pack_h2(pr3.x, pr3.y); q1.w = pack_h2(pr3.z, pr3.w);
            *(uint4*)(stsP + bo) = q0;
            *(uint4*)(stsP + bo + 16) = q1;
        }
        __syncthreads();
        if (kc < 7) {
            const float* Xn = Xp + (kc + 1) * 32;
            pr0 = *(const float4*)(Xn + 0);
            pr1 = *(const float4*)(Xn + 4);
            pr2 = *(const float4*)(Xn + 8);
            pr3 = *(const float4*)(Xn + 12);
        }
#pragma unroll
        for (int ks = 0; ks < 2; ks++) {
            uint32_t Ar[4][4], Br[2][4];
#pragma unroll
            for (int mt = 0; mt < 4; mt++)
                LDSM4(Ar[mt], aAddr0 + bo + mt * (16 * 80) + ks * 32);
#pragma unroll
            for (int np = 0; np < 2; np++)
                LDSM4(Br[np], bAddr0 + np * (16 * 528) + kc * 64 + ks * 32);
#pragma unroll
            for (int mt = 0; mt < 4; mt++)
#pragma unroll
                for (int nt = 0; nt < 4; nt++)
                    MMA16816(acc[mt][nt], Ar[mt], Br[nt >> 1][(nt & 1) * 2],
                             Br[nt >> 1][(nt & 1) * 2 + 1]);
        }
    }

    float b0r[4], b1r[4];
#pragma unroll
    for (int nt = 0; nt < 4; nt++) {
        b0r[nt] = b2s[wn * 32 + nt * 8 + tig * 2];
        b1r[nt] = b2s[wn * 32 + nt * 8 + tig * 2 + 1];
    }
#pragma unroll
    for (int mt = 0; mt < 4; mt++) {
        int rA = row0 + wm * 64 + mt * 16 + g;
        int rB = rA + 8;
#pragma unroll
        for (int nt = 0; nt < 4; nt++) {
            int e = e0 + wn * 32 + nt * 8 + tig * 2;
            float2 vA = make_float2(ftanh(acc[mt][nt][0] + b0r[nt]),
                                    ftanh(acc[mt][nt][1] + b1r[nt]));
            float2 vB = make_float2(ftanh(acc[mt][nt][2] + b0r[nt]),
                                    ftanh(acc[mt][nt][3] + b1r[nt]));
            *(float2*)&g_x2[(size_t)rA * EE + e] = vA;
            *(float2*)&g_x2[(size_t)rB * EE + e] = vB;
        }
    }
}

// ---------------------------------------------------------------------------
// K2 (PERSISTENT + E-SPLIT): grid (NSM, 2).  Each CTA owns a 128-e half of
// W1 (loaded once) and loops over tiles with cross-tile A prefetch.  2 CTAs
// co-reside per SM (90.7KB smem, <=128 regs) -> 4 warps/SMSP from
// independent barrier domains fill the LDSM/MMA latency bubbles.
// Inner loop = R8-verified e-split code (f16 acc, rate-equal per R15).
// ---------------------------------------------------------------------------
#define OFF_B1  0        // 512 B
#define OFF_X2  512      // 4*132*4 = 2112 -> ends 2624
#define OFF_BW  2688     // 128*528 = 67584 -> ends 70272
#define OFF_A   70272    // 2 * 10240 -> ends 90752
#define A_BUF   10240
#define K2_SMEM 90752

__global__ __launch_bounds__(256, 2) void k2_scores(const float* __restrict__ X,
                                                    const float* __restrict__ b1) {
    extern __shared__ __align__(16) char smem[];
    float* b1s = (float*)(smem + OFF_B1);
    float* x2s = (float*)(smem + OFF_X2);

    const int tid = threadIdx.x;
    const int w = tid >> 5, lane = tid & 31;
    const int tig = lane & 3, g = lane >> 2;
    const int wm = w >> 2, wn = w & 3;
    const int e0 = blockIdx.y * 128;

    // ---- one-time: W1 e-half (fp16) -> padded smem, b1 half -> smem ----
    {
        const uint4* Wp = (const uint4*)(g_w1h + (size_t)e0 * FF);
        for (int i = tid; i < 4096; i += 256) {
            int r = i >> 5, s2 = i & 31;
            *(uint4*)(smem + OFF_BW + r * 528 + s2 * 16) = Wp[i];
        }
    }
    if (tid < 128) b1s[tid] = b1[e0 + tid];

    const uint32_t sb = smem_u32(smem);
    const int arow = lane & 15, asel = lane >> 4;
    const uint32_t aAddr0 = sb + OFF_A + (uint32_t)(wm * 64 + arow) * 80 + asel * 16;
    const int brow = (lane & 7) + ((lane >> 4) << 3), bsel = (lane >> 3) & 1;
    const uint32_t bAddr0 = sb + OFF_BW + (uint32_t)(wn * 32 + brow) * 528 + bsel * 16;
    char* stsP = smem + OFF_A + (tid >> 1) * 80 + (tid & 1) * 32;

    const float* XpBase = X + (size_t)(tid >> 1) * FF + (tid & 1) * 16;
    const int G = gridDim.x;

    // prefetch chunk 0 of first tile
    {
        const float* Xp0 = XpBase + (size_t)blockIdx.x * 128 * FF;
        float4 pr0 = *(const float4*)(Xp0 + 0);
        float4 pr1 = *(const float4*)(Xp0 + 4);
        float4 pr2 = *(const float4*)(Xp0 + 8);
        float4 pr3 = *(const float4*)(Xp0 + 12);
        const float inv = 1.f / (float)PP;

        for (int t = blockIdx.x; t < NTILES; t += G) {
            const int row0 = t * 128;
            const int n0 = row0 / PP;
            const float* XpCur = XpBase + (size_t)row0 * FF;
            const float* XpNext = XpBase + ((size_t)row0 + (size_t)G * 128) * FF;
            const bool hasNext = (t + G) < NTILES;

            // x2 slice (this e-half) for this tile
            for (int i = tid; i < 4 * 128; i += 256) {
                int s = i >> 7, e = i & 127;
                int n = n0 + s;
                x2s[s * 132 + e] = (n < NN) ? g_x2[(size_t)n * EE + e0 + e] : 0.f;
            }

            uint32_t acc16[4][4][2];
#pragma unroll
            for (int mt = 0; mt < 4; mt++)
#pragma unroll
                for (int nt = 0; nt < 4; nt++) {
                    acc16[mt][nt][0] = 0u;
                    acc16[mt][nt][1] = 0u;
                }

            for (int kc = 0; kc < 8; kc++) {
                const uint32_t bo = (kc & 1) * A_BUF;
                {
                    uint4 q0, q1;
                    q0.x = pack_h2(pr0.x, pr0.y); q0.y = pack_h2(pr0.z, pr0.w);
                    q0.z = pack_h2(pr1.x, pr1.y); q0.w = pack_h2(pr1.z, pr1.w);
                    q1.x = pack_h2(pr2.x, pr2.y); q1.y = pack_h2(pr2.z, pr2.w);
                    q1.z = pack_h2(pr3.x, pr3.y); q1.w = pack_h2(pr3.z, pr3.w);
                    *(uint4*)(stsP + bo) = q0;
                    *(uint4*)(stsP + bo + 16) = q1;
                }
                __syncthreads();
                if (kc < 7) {
                    const float* Xn = XpCur + (kc + 1) * 32;
                    pr0 = *(const float4*)(Xn + 0);
                    pr1 = *(const float4*)(Xn + 4);
                    pr2 = *(const float4*)(Xn + 8);
                    pr3 = *(const float4*)(Xn + 12);
                } else if (hasNext) {
                    pr0 = *(const float4*)(XpNext + 0);
                    pr1 = *(const float4*)(XpNext + 4);
                    pr2 = *(const float4*)(XpNext + 8);
                    pr3 = *(const float4*)(XpNext + 12);
                }
#pragma unroll
                for (int ks = 0; ks < 2; ks++) {
                    uint32_t Ar[4][4], Br[2][4];
#pragma unroll
                    for (int mt = 0; mt < 4; mt++)
                        LDSM4(Ar[mt], aAddr0 + bo + mt * (16 * 80) + ks * 32);
#pragma unroll
                    for (int np = 0; np < 2; np++)
                        LDSM4(Br[np], bAddr0 + np * (16 * 528) + kc * 64 + ks * 32);
#pragma unroll
                    for (int mt = 0; mt < 4; mt++)
#pragma unroll
                        for (int nt = 0; nt < 4; nt++)
                            MMA16816F16(acc16[mt][nt], Ar[mt],
                                        Br[nt >> 1][(nt & 1) * 2],
                                        Br[nt >> 1][(nt & 1) * 2 + 1]);
                }
            }

            // ---- epilogue (partial dot over this e-half) ----
#pragma unroll
            for (int mt = 0; mt < 4; mt++) {
                int rA = wm * 64 + mt * 16 + g;
                int rB = rA + 8;
                int nA = (row0 + rA) / PP;
                int nB = (row0 + rB) / PP;
                const float* xA = x2s + (nA - n0) * 132 + wn * 32;
                const float* xB = x2s + (nB - n0) * 132 + wn * 32;
                float sA = 0.f, sB = 0.f;
#pragma unroll
                for (int nt = 0; nt < 4; nt++) {
                    int c0 = nt * 8 + tig * 2, c1 = c0 + 1;
                    float bb0 = b1s[wn * 32 + c0];
                    float bb1 = b1s[wn * 32 + c1];
                    float2 lo = __half22float2(*(__half2*)&acc16[mt][nt][0]);
                    float2 hi = __half22float2(*(__half2*)&acc16[mt][nt][1]);
                    sA += tanha(lo.x + bb0) * xA[c0] + tanha(lo.y + bb1) * xA[c1];
                    sB += tanha(hi.x + bb0) * xB[c0] + tanha(hi.y + bb1) * xB[c1];
                }
                sA += __shfl_xor_sync(0xffffffffu, sA, 1);
                sA += __shfl_xor_sync(0xffffffffu, sA, 2);
                sB += __shfl_xor_sync(0xffffffffu, sB, 1);
                sB += __shfl_xor_sync(0xffffffffu, sB, 2);
                if (tig == 0) {
                    atomicAdd(&g_scores[nA], sA * inv);
                    atomicAdd(&g_scores[nB], sB * inv);
                }
            }
            __syncthreads();   // protect x2s before next tile's overwrite
        }
    }
}

// ---------------------------------------------------------------------------
// K3: per-segment softmax over scalar scores (patch_lens int32 or int64).
// ---------------------------------------------------------------------------
__device__ __forceinline__ int seg_len(const int* p32, int is64, int i) {
    return is64 ? p32[2 * i] : p32[i];
}

__global__ __launch_bounds__(128) void k3_softmax(const int* __restrict__ lens32) {
    __shared__ float sh[128];
    __shared__ int s_off, s_len;
    int s = blockIdx.x, tid = threadIdx.x;
    if (tid == 0) {
        int is64 = (lens32[1] == 0) ? 1 : 0;
        int o = 0;
        for (int i = 0; i < s; i++) o += seg_len(lens32, is64, i);
        s_off = o;
        s_len = seg_len(lens32, is64, s);
    }
    __syncthreads();
    int off = s_off, len = s_len;
    float v = (tid < len) ? g_scores[off + tid] : -1e30f;
    sh[tid] = v;
    __syncthreads();
    for (int st = 64; st > 0; st >>= 1) {
        if (tid < st) sh[tid] = fmaxf(sh[tid], sh[tid + st]);
        __syncthreads();
    }
    float m = sh[0];
    __syncthreads();
    float e = (tid < len) ? expf(v - m) : 0.f;
    sh[tid] = e;
    __syncthreads();
    for (int st = 64; st > 0; st >>= 1) {
        if (tid < st) sh[tid] += sh[tid + st];
        __syncthreads();
    }
    float z = sh[0];
    if (tid < len) g_attn[off + tid] = e / z;
}

// ---------------------------------------------------------------------------
// K4: out[n,f] = attn[n] * sum_p x[n,p,f]   (R4-proven, ~82% DRAM peak)
// ---------------------------------------------------------------------------
__global__ __launch_bounds__(256) void k4_out(const float* __restrict__ X,
                                              float* __restrict__ out) {
    int n = blockIdx.x, f = threadIdx.x;
    const float* xp = X + (size_t)n * PP * FF + f;
    float acc = 0.f;
#pragma unroll
    for (int p = 0; p < PP; p++) acc += xp[(size_t)p * FF];
    out[(size_t)n * FF + f] = acc * g_attn[n];
}

// ---------------------------------------------------------------------------
extern "C" void kernel_launch(void* const* d_in, const int* in_sizes, int n_in,
                              void* d_out, int out_size) {
    const float* x      = (const float*)d_in[0];
    const float* hidden = (const float*)d_in[1];
    const float* W1     = (const float*)d_in[2];
    const float* b1     = (const float*)d_in[3];
    const float* W2     = (const float*)d_in[4];
    const float* b2     = (const float*)d_in[5];
    const int* pl       = (const int*)d_in[6];

    float* out = (float*)d_out;

    static bool s_init = false;
    static int s_nsm = 148;
    if (!s_init) {
        cudaFuncSetAttribute(k2_scores, cudaFuncAttributeMaxDynamicSharedMemorySize, K2_SMEM);
        cudaFuncSetAttribute(k1m_x2, cudaFuncAttributeMaxDynamicSharedMemorySize, K1M_SMEM);
        int dev = 0, nsm = 0;
        cudaGetDevice(&dev);
        if (cudaDeviceGetAttribute(&nsm, cudaDevAttrMultiProcessorCount, dev) == cudaSuccess && nsm > 0)
            s_nsm = nsm;
        s_init = true;
    }

    // fully serial, default stream; k2 at launch slot 4 (ncu capture)
    k0_prep<<<256, 256>>>(W1, W2);
    kdummy<<<1, 32>>>();
    k1m_x2<<<dim3(64, 2), 256, K1M_SMEM>>>(hidden, b2);
    k2_scores<<<dim3(s_nsm, 2), 256, K2_SMEM>>>(x, b1);
    k3_softmax<<<SS, 128>>>(pl);
    k4_out<<<NN, 256>>>(x, out);
}